// round 6
// baseline (speedup 1.0000x reference)
#include <cuda_runtime.h>
#include <stdint.h>

#define NB 32
#define CI 32
#define CO 32
#define HH 128
#define WW 128

// Scratch (static __device__ arrays: allocation-free, graph-safe)
__device__ signed char g_act_nhwc[(size_t)NB * HH * WW * CI];  // 16 MB NHWC int8
__device__ int g_max;
__device__ unsigned g_wpack[CO * 9 * 8];                       // packed weights

// pack weights (Co,Ci,3,3) int32 -> g_wpack[(co*9+tap)*8 + ci/4]; also reset g_max
__global__ void k_packw(const int* __restrict__ w) {
    int i = blockIdx.x * blockDim.x + threadIdx.x;
    if (i == 0) g_max = 0;
    if (i >= CO * 9 * 8) return;
    int ciw = i & 7;
    int t = (i >> 3) % 9;
    int co = i / 72;
    int kh = t / 3, kw = t - kh * 3;
    unsigned v = 0;
#pragma unroll
    for (int j = 0; j < 4; j++) {
        int ci = ciw * 4 + j;
        unsigned b = (unsigned)(w[((co * CI + ci) * 3 + kh) * 3 + kw]) & 0xFFu;
        v |= b << (8 * j);
    }
    g_wpack[i] = v;
}

// NCHW int32 -> NHWC int8 (4 ci per word, ci0 in low byte)
__global__ void k_transpose(const int* __restrict__ act) {
    int p = blockIdx.x * blockDim.x + threadIdx.x;
    int x = p & (WW - 1);
    int y = (p >> 7) & (HH - 1);
    int n = p >> 14;
    unsigned* dst = (unsigned*)(g_act_nhwc + (size_t)p * CI);
#pragma unroll
    for (int j = 0; j < 8; j++) {
        unsigned v = 0;
#pragma unroll
        for (int b = 0; b < 4; b++) {
            int ci = j * 4 + b;
            unsigned c = (unsigned)(act[((size_t)(n * CI + ci) * HH + y) * WW + x]) & 0xFFu;
            v |= c << (8 * b);
        }
        dst[j] = v;
    }
}

__device__ __forceinline__ void mma_s8(int d[4], unsigned a0, unsigned a1,
                                       unsigned a2, unsigned a3,
                                       unsigned b0, unsigned b1) {
    asm volatile(
        "mma.sync.aligned.m16n8k32.row.col.s32.s8.s8.s32 "
        "{%0,%1,%2,%3}, {%4,%5,%6,%7}, {%8,%9}, {%0,%1,%2,%3};\n"
        : "+r"(d[0]), "+r"(d[1]), "+r"(d[2]), "+r"(d[3])
        : "r"(a0), "r"(a1), "r"(a2), "r"(a3), "r"(b0), "r"(b1));
}

// Bit-exact replica of psto_shift + act_calc select paths.
__device__ __forceinline__ float quantize_one(int v, int shift, int eff) {
    if (shift < 1) return (float)(signed char)v;  // truncating int8 cast
    int rt = v >> eff;                            // floor division by 2^eff
    int prob = v & ((1 << eff) - 1);              // non-negative remainder
    int h = eff >> 1;
    int qp = prob >> h;
    int pr = prob & ((1 << h) - 1);
    if (eff & 1) pr <<= 1;
    int sgn = (v > 0) - (v < 0);
    int r = rt + ((qp <= pr) ? 0 : sgn);
    r = r < -127 ? -127 : (r > 127 ? 127 : r);
    return (float)r;
}

// Implicit-GEMM conv via warp IMMA. Block = 2 output rows (n fixed).
// 8 warps: warp w -> row (w>>2), x-segment (w&3)*32. Warp tile = 32 px x 32 co.
// MODE 0: max-reduction only (no stores). MODE 1: quantize + float store.
template <int MODE>
__global__ void __launch_bounds__(256) k_conv(const int* __restrict__ expin,
                                              const int* __restrict__ wexp,
                                              float* __restrict__ out,
                                              int out_size) {
    __shared__ signed char s_act[4 * 130 * 32];  // rows y0-1..y0+2, x halo
    __shared__ unsigned s_w[9 * 32 * 8];         // [tap][co][ciw]

    int tid = threadIdx.x;
    int b = blockIdx.x;
    int n = b >> 6;
    int y0 = (b & 63) << 1;

    uint4* sa4 = (uint4*)s_act;
#pragma unroll
    for (int i = tid; i < 4 * 130 * 32 / 16; i += 256) sa4[i] = make_uint4(0, 0, 0, 0);
    for (int i = tid; i < 9 * 32 * 8; i += 256) {
        int ciw = i & 7;
        int co = (i >> 3) & 31;
        int t = i >> 8;
        s_w[i] = g_wpack[(co * 9 + t) * 8 + ciw];
    }
    __syncthreads();

    {
        int px = tid >> 1;
        int half = (tid & 1) << 4;
#pragma unroll
        for (int r = 0; r < 4; r++) {
            int iy = y0 + r - 1;
            if ((unsigned)iy < HH) {
                const uint4* src = (const uint4*)(g_act_nhwc +
                    ((((size_t)n * HH + iy) * WW + px) << 5) + half);
                *(uint4*)(s_act + ((r * 130 + px + 1) * 32) + half) = *src;
            }
        }
    }
    __syncthreads();

    int lane = tid & 31;
    int wid = tid >> 5;
    int g = lane >> 2;
    int tig = lane & 3;
    int row = wid >> 2;
    int xbase = (wid & 3) << 5;

    int acc[2][4][4];
#pragma unroll
    for (int m = 0; m < 2; m++)
#pragma unroll
        for (int ns = 0; ns < 4; ns++)
#pragma unroll
            for (int k = 0; k < 4; k++) acc[m][ns][k] = 0;

#pragma unroll 1
    for (int t = 0; t < 9; t++) {
        int ky = t / 3, kx = t - 3 * (t / 3);
        const signed char* arow = s_act + ((row + ky) * 130 + xbase + kx) * 32;
        unsigned a0[2], a1[2], a2[2], a3[2];
#pragma unroll
        for (int m = 0; m < 2; m++) {
            const unsigned* p0 = (const unsigned*)(arow + (m * 16 + g) * 32) + tig;
            const unsigned* p1 = (const unsigned*)(arow + (m * 16 + g + 8) * 32) + tig;
            a0[m] = p0[0];
            a2[m] = p0[4];
            a1[m] = p1[0];
            a3[m] = p1[4];
        }
#pragma unroll
        for (int ns = 0; ns < 4; ns++) {
            const unsigned* pw = &s_w[(t * 32 + ns * 8 + g) * 8 + tig];
            unsigned b0 = pw[0], b1 = pw[4];
#pragma unroll
            for (int m = 0; m < 2; m++)
                mma_s8(acc[m][ns], a0[m], a1[m], a2[m], a3[m], b0, b1);
        }
    }

    int y = y0 + row;

    if (MODE == 0) {
        // global |max| reduction only
        int mloc = 0;
#pragma unroll
        for (int m = 0; m < 2; m++)
#pragma unroll
            for (int ns = 0; ns < 4; ns++)
#pragma unroll
                for (int k = 0; k < 4; k++) {
                    int a = acc[m][ns][k];
                    mloc = max(mloc, a < 0 ? -a : a);
                }
        mloc = __reduce_max_sync(0xffffffffu, mloc);
        if (lane == 0) atomicMax(&g_max, mloc);
    } else {
        int gmax = g_max;
        int bw = gmax ? (32 - __clz(gmax - 1)) : 0;  // exact ceil(log2)
        int shift = bw - 7;
        int eff = shift > 1 ? shift : 2;

#pragma unroll
        for (int m = 0; m < 2; m++)
#pragma unroll
            for (int ns = 0; ns < 4; ns++) {
                int x0p = xbase + m * 16 + g;
                int co0 = ns * 8 + tig * 2;
                float* base0 = out + (((n * 32 + co0) * 128 + y) * 128);
                float* base1 = base0 + 128 * 128;
                base0[x0p] = quantize_one(acc[m][ns][0], shift, eff);
                base1[x0p] = quantize_one(acc[m][ns][1], shift, eff);
                base0[x0p + 8] = quantize_one(acc[m][ns][2], shift, eff);
                base1[x0p + 8] = quantize_one(acc[m][ns][3], shift, eff);
            }

        if (b == 0 && tid == 0) {
            int inc = shift > 1 ? shift : (shift == 1 ? 2 : 0);
            int e = expin[0] + wexp[0] + inc;
            out[out_size - 1] = (float)(signed char)e;
        }
    }
}

extern "C" void kernel_launch(void* const* d_in, const int* in_sizes, int n_in,
                              void* d_out, int out_size) {
    const int* act = (const int*)d_in[0];
    const int* expin = (const int*)d_in[1];
    const int* w = (const int*)d_in[2];
    const int* wexp = (const int*)d_in[3];
    float* out = (float*)d_out;

    k_packw<<<(CO * 9 * 8 + 255) / 256, 256>>>(w);
    k_transpose<<<(NB * HH * WW) / 256, 256>>>(act);
    k_conv<0><<<NB * 64, 256>>>(expin, wexp, out, out_size);  // max pass
    k_conv<1><<<NB * 64, 256>>>(expin, wexp, out, out_size);  // quantize pass
}

// round 7
// speedup vs baseline: 1.2938x; 1.2938x over previous
#include <cuda_runtime.h>
#include <stdint.h>

#define NB 32
#define CI 32
#define CO 32
#define HH 128
#define WW 128

// Scratch (static __device__ arrays: allocation-free, graph-safe)
__device__ signed char g_act_nhwc[(size_t)NB * HH * WW * CI];  // 16 MB NHWC int8
__device__ int g_max;
__device__ unsigned g_wpack[CO * 9 * 8];                       // packed weights

// NCHW int32 -> NHWC int8; block 0 also packs weights + resets g_max
__global__ void k_transpose(const int* __restrict__ act, const int* __restrict__ w) {
    int p = blockIdx.x * blockDim.x + threadIdx.x;
    int x = p & (WW - 1);
    int y = (p >> 7) & (HH - 1);
    int n = p >> 14;
    unsigned* dst = (unsigned*)(g_act_nhwc + (size_t)p * CI);
#pragma unroll
    for (int j = 0; j < 8; j++) {
        unsigned v = 0;
#pragma unroll
        for (int b = 0; b < 4; b++) {
            int ci = j * 4 + b;
            unsigned c = (unsigned)(act[((size_t)(n * CI + ci) * HH + y) * WW + x]) & 0xFFu;
            v |= c << (8 * b);
        }
        dst[j] = v;
    }
    if (blockIdx.x == 0) {
        if (threadIdx.x == 0) g_max = 0;
        for (int i = threadIdx.x; i < CO * 9 * 8; i += blockDim.x) {
            int ciw = i & 7;
            int t = (i >> 3) % 9;
            int co = i / 72;
            int kh = t / 3, kw = t - kh * 3;
            unsigned v = 0;
#pragma unroll
            for (int j = 0; j < 4; j++) {
                int ci = ciw * 4 + j;
                unsigned b = (unsigned)(w[((co * CI + ci) * 3 + kh) * 3 + kw]) & 0xFFu;
                v |= b << (8 * j);
            }
            g_wpack[i] = v;
        }
    }
}

__device__ __forceinline__ void mma_s8(int d[4], const unsigned a[4],
                                       unsigned b0, unsigned b1) {
    asm volatile(
        "mma.sync.aligned.m16n8k32.row.col.s32.s8.s8.s32 "
        "{%0,%1,%2,%3}, {%4,%5,%6,%7}, {%8,%9}, {%0,%1,%2,%3};\n"
        : "+r"(d[0]), "+r"(d[1]), "+r"(d[2]), "+r"(d[3])
        : "r"(a[0]), "r"(a[1]), "r"(a[2]), "r"(a[3]), "r"(b0), "r"(b1));
}

__device__ __forceinline__ void ldm4(unsigned r[4], unsigned saddr) {
    asm volatile(
        "ldmatrix.sync.aligned.m8n8.x4.shared.b16 {%0,%1,%2,%3}, [%4];\n"
        : "=r"(r[0]), "=r"(r[1]), "=r"(r[2]), "=r"(r[3])
        : "r"(saddr));
}

// swizzle: XOR bit4 with bit7 of the byte offset (16B-half swap every 4 pixels)
__device__ __forceinline__ unsigned swz(unsigned off) {
    return off ^ ((off >> 3) & 16);
}

// Bit-exact replica of psto_shift + act_calc select paths.
__device__ __forceinline__ float quantize_one(int v, int shift, int eff) {
    if (shift < 1) return (float)(signed char)v;  // truncating int8 cast
    int rt = v >> eff;                            // floor division by 2^eff
    int prob = v & ((1 << eff) - 1);              // non-negative remainder
    int h = eff >> 1;
    int qp = prob >> h;
    int pr = prob & ((1 << h) - 1);
    if (eff & 1) pr <<= 1;
    int sgn = (v >> 31) | 1;                      // +-1; v==0 path never decrements
    int r = rt + ((qp <= pr) ? 0 : sgn);
    r = r < -127 ? -127 : (r > 127 ? 127 : r);
    return (float)r;
}

// Implicit-GEMM conv via IMMA + ldmatrix. Block = 2 output rows (n fixed).
// 8 warps: warp w -> row (w>>2), x-segment (w&3)*32. Warp tile = 32 px x 32 co.
// MODE 0: |max| reduction only. MODE 1: quantize + float store.
template <int MODE>
__global__ void __launch_bounds__(256) k_conv(const int* __restrict__ expin,
                                              const int* __restrict__ wexp,
                                              float* __restrict__ out,
                                              int out_size) {
    __shared__ __align__(128) signed char s_act[4 * 130 * 32];  // swizzled
    __shared__ __align__(128) signed char s_w[9 * 32 * 32];     // swizzled

    int tid = threadIdx.x;
    int b = blockIdx.x;
    int n = b >> 6;
    int y0 = (b & 63) << 1;

    // zero act tile (halo); swizzle irrelevant for zeros
    uint4* sa4 = (uint4*)s_act;
#pragma unroll
    for (int i = tid; i < 4 * 130 * 32 / 16; i += 256) sa4[i] = make_uint4(0, 0, 0, 0);
    // weights: (co,t,8 words) -> s_w[t][co] 32B rows, swizzled, 16B at a time
    for (int i = tid; i < 9 * 32 * 2; i += 256) {
        int h = i & 1;
        int co = (i >> 1) & 31;
        int t = i >> 6;
        unsigned off = ((unsigned)(t * 32 + co) << 5) + (h << 4);
        *(uint4*)(s_w + swz(off)) = ((const uint4*)g_wpack)[(co * 9 + t) * 2 + h];
    }
    __syncthreads();

    // fill interior: 4 rows x 128 px x 32B, swizzled
    {
        int px = tid >> 1;
        int half = (tid & 1) << 4;
#pragma unroll
        for (int r = 0; r < 4; r++) {
            int iy = y0 + r - 1;
            if ((unsigned)iy < HH) {
                const uint4* src = (const uint4*)(g_act_nhwc +
                    ((((size_t)n * HH + iy) * WW + px) << 5) + half);
                unsigned off = ((unsigned)((r * 130 + px + 1) << 5)) + half;
                *(uint4*)(s_act + swz(off)) = *src;
            }
        }
    }
    __syncthreads();

    int lane = tid & 31;
    int wid = tid >> 5;
    int row = wid >> 2;
    int xbase = (wid & 3) << 5;

    unsigned actS = (unsigned)__cvta_generic_to_shared(s_act);
    unsigned wS = (unsigned)__cvta_generic_to_shared(s_w);

    // ldmatrix lane bases
    // A: matrices {px0-7 klo, px8-15 klo, px0-7 khi, px8-15 khi}
    unsigned abase = ((unsigned)(row * 130 + xbase + (lane & 15)) << 5) +
                     ((lane >> 4) << 4);
    // B: matrices {co0-7 klo, co0-7 khi, co8-15 klo, co8-15 khi}
    unsigned bbase = ((unsigned)(((lane >> 4) << 3) + (lane & 7)) << 5) +
                     (((lane >> 3) & 1) << 4);

    int acc[2][4][4];
#pragma unroll
    for (int m = 0; m < 2; m++)
#pragma unroll
        for (int ns = 0; ns < 4; ns++)
#pragma unroll
            for (int k = 0; k < 4; k++) acc[m][ns][k] = 0;

#pragma unroll
    for (int t = 0; t < 9; t++) {
        const int ky = t / 3, kx = t - 3 * (t / 3);
        unsigned af[2][4], bf[2][4];
        unsigned ao = abase + ((unsigned)(ky * 130 + kx) << 5);
        ldm4(af[0], actS + swz(ao));
        ldm4(af[1], actS + swz(ao + 512));
        unsigned bo = bbase + ((unsigned)t << 10);
        ldm4(bf[0], wS + swz(bo));
        ldm4(bf[1], wS + swz(bo + 512));
#pragma unroll
        for (int m = 0; m < 2; m++) {
            mma_s8(acc[m][0], af[m], bf[0][0], bf[0][1]);
            mma_s8(acc[m][1], af[m], bf[0][2], bf[0][3]);
            mma_s8(acc[m][2], af[m], bf[1][0], bf[1][1]);
            mma_s8(acc[m][3], af[m], bf[1][2], bf[1][3]);
        }
    }

    int y = y0 + row;
    int g = lane >> 2;
    int tig = lane & 3;

    if (MODE == 0) {
        int mloc = 0;
#pragma unroll
        for (int m = 0; m < 2; m++)
#pragma unroll
            for (int ns = 0; ns < 4; ns++)
#pragma unroll
                for (int k = 0; k < 4; k++) {
                    int a = acc[m][ns][k];
                    mloc = max(mloc, a < 0 ? -a : a);
                }
        mloc = __reduce_max_sync(0xffffffffu, mloc);
        if (lane == 0) atomicMax(&g_max, mloc);
    } else {
        int gmax = g_max;
        int bw = gmax ? (32 - __clz(gmax - 1)) : 0;  // exact ceil(log2)
        int shift = bw - 7;
        int eff = shift > 1 ? shift : 2;

#pragma unroll
        for (int m = 0; m < 2; m++)
#pragma unroll
            for (int ns = 0; ns < 4; ns++) {
                int x0p = xbase + m * 16 + g;
                int co0 = ns * 8 + tig * 2;
                float* base0 = out + (((n * 32 + co0) * 128 + y) * 128);
                float* base1 = base0 + 128 * 128;
                base0[x0p] = quantize_one(acc[m][ns][0], shift, eff);
                base1[x0p] = quantize_one(acc[m][ns][1], shift, eff);
                base0[x0p + 8] = quantize_one(acc[m][ns][2], shift, eff);
                base1[x0p + 8] = quantize_one(acc[m][ns][3], shift, eff);
            }

        if (b == 0 && tid == 0) {
            int inc = shift > 1 ? shift : (shift == 1 ? 2 : 0);
            int e = expin[0] + wexp[0] + inc;
            out[out_size - 1] = (float)(signed char)e;
        }
    }
}

extern "C" void kernel_launch(void* const* d_in, const int* in_sizes, int n_in,
                              void* d_out, int out_size) {
    const int* act = (const int*)d_in[0];
    const int* expin = (const int*)d_in[1];
    const int* w = (const int*)d_in[2];
    const int* wexp = (const int*)d_in[3];
    float* out = (float*)d_out;

    k_transpose<<<(NB * HH * WW) / 256, 256>>>(act, w);
    k_conv<0><<<NB * 64, 256>>>(expin, wexp, out, out_size);  // max pass
    k_conv<1><<<NB * 64, 256>>>(expin, wexp, out, out_size);  // quantize pass
}

// round 9
// speedup vs baseline: 1.4386x; 1.1119x over previous
#include <cuda_runtime.h>
#include <stdint.h>

#define NB 32
#define CI 32
#define CO 32
#define HH 128
#define WW 128

// Scratch (static __device__ arrays: allocation-free, graph-safe)
__device__ signed char g_act_nhwc[(size_t)NB * HH * WW * CI];  // 16 MB NHWC int8
__device__ int g_max;
__device__ unsigned g_wpack[CO * 9 * 8];                       // packed weights

// NCHW int32 -> NHWC int8. One thread = one 16B output chunk (pixel, ci-half).
// Reads: 64B-coalesced per ci; writes: fully contiguous STG.128.
// Block 0 also packs weights + resets g_max.
__global__ void k_transpose(const int* __restrict__ act, const int* __restrict__ w) {
    int idx = blockIdx.x * blockDim.x + threadIdx.x;  // NB*HH*WW*2 threads
    int half = idx & 1;
    int p = idx >> 1;              // pixel: n*16384 + y*128 + x
    int x = p & (WW - 1);
    int y = (p >> 7) & (HH - 1);
    int n = p >> 14;

    const int* src = act + ((size_t)(n * CI + half * 16) * HH + y) * WW + x;
    unsigned vv[4];
#pragma unroll
    for (int j = 0; j < 4; j++) {
        unsigned v = 0;
#pragma unroll
        for (int bb = 0; bb < 4; bb++) {
            unsigned c = (unsigned)src[(size_t)(j * 4 + bb) * HH * WW] & 0xFFu;
            v |= c << (8 * bb);
        }
        vv[j] = v;
    }
    *(uint4*)(g_act_nhwc + ((size_t)p << 5) + (half << 4)) =
        make_uint4(vv[0], vv[1], vv[2], vv[3]);

    if (blockIdx.x == 0) {
        if (threadIdx.x == 0) g_max = 0;
        for (int i = threadIdx.x; i < CO * 9 * 8; i += blockDim.x) {
            int ciw = i & 7;
            int t = (i >> 3) % 9;
            int co = i / 72;
            int kh = t / 3, kw = t - kh * 3;
            unsigned v = 0;
#pragma unroll
            for (int j = 0; j < 4; j++) {
                int ci = ciw * 4 + j;
                unsigned b = (unsigned)(w[((co * CI + ci) * 3 + kh) * 3 + kw]) & 0xFFu;
                v |= b << (8 * j);
            }
            g_wpack[i] = v;
        }
    }
}

__device__ __forceinline__ void mma_s8(int d[4], const unsigned a[4],
                                       unsigned b0, unsigned b1) {
    asm volatile(
        "mma.sync.aligned.m16n8k32.row.col.s32.s8.s8.s32 "
        "{%0,%1,%2,%3}, {%4,%5,%6,%7}, {%8,%9}, {%0,%1,%2,%3};\n"
        : "+r"(d[0]), "+r"(d[1]), "+r"(d[2]), "+r"(d[3])
        : "r"(a[0]), "r"(a[1]), "r"(a[2]), "r"(a[3]), "r"(b0), "r"(b1));
}

__device__ __forceinline__ void ldm4(unsigned r[4], unsigned saddr) {
    asm volatile(
        "ldmatrix.sync.aligned.m8n8.x4.shared.b16 {%0,%1,%2,%3}, [%4];\n"
        : "=r"(r[0]), "=r"(r[1]), "=r"(r[2]), "=r"(r[3])
        : "r"(saddr));
}

// swizzle: XOR bit4 with bit7 of the byte offset
__device__ __forceinline__ unsigned swz(unsigned off) {
    return off ^ ((off >> 3) & 16);
}

// Bit-exact replica of psto_shift + act_calc select paths.
__device__ __forceinline__ float quantize_one(int v, int shift, int eff) {
    if (shift < 1) return (float)(signed char)v;  // truncating int8 cast
    int rt = v >> eff;                            // floor division by 2^eff
    int prob = v & ((1 << eff) - 1);              // non-negative remainder
    int h = eff >> 1;
    int qp = prob >> h;
    int pr = prob & ((1 << h) - 1);
    if (eff & 1) pr <<= 1;
    int sgn = (v >> 31) | 1;                      // v==0 never decrements (prob=0)
    int r = rt + ((qp <= pr) ? 0 : sgn);
    r = r < -127 ? -127 : (r > 127 ? 127 : r);
    return (float)r;
}

// Implicit-GEMM conv via IMMA + ldmatrix. Block = 4 output rows (n fixed).
// 8 warps: warp w -> rows r0=(w>>2)*2 .. +1, x-segment (w&3)*32.
// Warp tile = 2 rows x 32 px x 32 co. MODE 0: |max| only. MODE 1: quantize+store.
template <int MODE>
__global__ void __launch_bounds__(256) k_conv(const int* __restrict__ expin,
                                              const int* __restrict__ wexp,
                                              float* __restrict__ out,
                                              int out_size) {
    __shared__ __align__(128) signed char s_act[6 * 130 * 32];  // swizzled
    __shared__ __align__(128) signed char s_w[9 * 32 * 32];     // swizzled

    int tid = threadIdx.x;
    int b = blockIdx.x;
    int n = b >> 5;
    int y0 = (b & 31) << 2;

    // zero act tile (halo rows/cols)
    uint4* sa4 = (uint4*)s_act;
#pragma unroll
    for (int i = tid; i < 6 * 130 * 32 / 16; i += 256) sa4[i] = make_uint4(0, 0, 0, 0);
    // weights: (co,t,8 words) -> s_w[t][co] 32B rows, swizzled, 16B at a time
    for (int i = tid; i < 9 * 32 * 2; i += 256) {
        int h = i & 1;
        int co = (i >> 1) & 31;
        int t = i >> 6;
        unsigned off = ((unsigned)(t * 32 + co) << 5) + (h << 4);
        *(uint4*)(s_w + swz(off)) = ((const uint4*)g_wpack)[(co * 9 + t) * 2 + h];
    }
    __syncthreads();

    // fill interior: 6 rows x 128 px x 32B, swizzled
    {
        int px = tid >> 1;
        int half = (tid & 1) << 4;
#pragma unroll
        for (int r = 0; r < 6; r++) {
            int iy = y0 + r - 1;
            if ((unsigned)iy < HH) {
                const uint4* src = (const uint4*)(g_act_nhwc +
                    ((((size_t)n * HH + iy) * WW + px) << 5) + half);
                unsigned off = ((unsigned)((r * 130 + px + 1) << 5)) + half;
                *(uint4*)(s_act + swz(off)) = *src;
            }
        }
    }
    __syncthreads();

    int lane = tid & 31;
    int wid = tid >> 5;
    int r0 = (wid >> 2) << 1;
    int xbase = (wid & 3) << 5;

    unsigned actS = (unsigned)__cvta_generic_to_shared(s_act);
    unsigned wS = (unsigned)__cvta_generic_to_shared(s_w);

    // ldmatrix lane-dependent base offsets
    unsigned alane = ((unsigned)(lane & 15) << 5) + ((lane >> 4) << 4);
    unsigned bbase = ((unsigned)(((lane >> 4) << 3) + (lane & 7)) << 5) +
                     (((lane >> 3) & 1) << 4);

    int acc[2][2][4][4];  // [row][m][ns][k]
#pragma unroll
    for (int rr = 0; rr < 2; rr++)
#pragma unroll
        for (int m = 0; m < 2; m++)
#pragma unroll
            for (int ns = 0; ns < 4; ns++)
#pragma unroll
                for (int k = 0; k < 4; k++) acc[rr][m][ns][k] = 0;

#pragma unroll
    for (int t = 0; t < 9; t++) {
        const int ky = t / 3, kx = t - 3 * (t / 3);
        unsigned bf[2][4];
        unsigned bo = bbase + ((unsigned)t << 10);
        ldm4(bf[0], wS + swz(bo));
        ldm4(bf[1], wS + swz(bo + 512));
#pragma unroll
        for (int rr = 0; rr < 2; rr++) {
            unsigned af[2][4];
            unsigned ao = alane +
                ((unsigned)((r0 + rr + ky) * 130 + xbase + kx) << 5);
            ldm4(af[0], actS + swz(ao));
            ldm4(af[1], actS + swz(ao + 512));
#pragma unroll
            for (int m = 0; m < 2; m++) {
                mma_s8(acc[rr][m][0], af[m], bf[0][0], bf[0][1]);
                mma_s8(acc[rr][m][1], af[m], bf[0][2], bf[0][3]);
                mma_s8(acc[rr][m][2], af[m], bf[1][0], bf[1][1]);
                mma_s8(acc[rr][m][3], af[m], bf[1][2], bf[1][3]);
            }
        }
    }

    int g = lane >> 2;
    int tig = lane & 3;

    if (MODE == 0) {
        int mloc = 0;
#pragma unroll
        for (int rr = 0; rr < 2; rr++)
#pragma unroll
            for (int m = 0; m < 2; m++)
#pragma unroll
                for (int ns = 0; ns < 4; ns++)
#pragma unroll
                    for (int k = 0; k < 4; k++) {
                        int a = acc[rr][m][ns][k];
                        mloc = max(mloc, a < 0 ? -a : a);
                    }
        mloc = __reduce_max_sync(0xffffffffu, mloc);
        if (lane == 0) atomicMax(&g_max, mloc);
    } else {
        int gmax = g_max;
        int bw = gmax ? (32 - __clz(gmax - 1)) : 0;  // exact ceil(log2)
        int shift = bw - 7;
        int eff = shift > 1 ? shift : 2;

#pragma unroll
        for (int rr = 0; rr < 2; rr++) {
            int y = y0 + r0 + rr;
#pragma unroll
            for (int m = 0; m < 2; m++)
#pragma unroll
                for (int ns = 0; ns < 4; ns++) {
                    int x0p = xbase + m * 16 + g;
                    int co0 = ns * 8 + tig * 2;
                    float* base0 = out + (((n * 32 + co0) * 128 + y) * 128);
                    float* base1 = base0 + 128 * 128;
                    base0[x0p] = quantize_one(acc[rr][m][ns][0], shift, eff);
                    base1[x0p] = quantize_one(acc[rr][m][ns][1], shift, eff);
                    base0[x0p + 8] = quantize_one(acc[rr][m][ns][2], shift, eff);
                    base1[x0p + 8] = quantize_one(acc[rr][m][ns][3], shift, eff);
                }
        }

        if (b == 0 && tid == 0) {
            int inc = shift > 1 ? shift : (shift == 1 ? 2 : 0);
            int e = expin[0] + wexp[0] + inc;
            out[out_size - 1] = (float)(signed char)e;
        }
    }
}

extern "C" void kernel_launch(void* const* d_in, const int* in_sizes, int n_in,
                              void* d_out, int out_size) {
    const int* act = (const int*)d_in[0];
    const int* expin = (const int*)d_in[1];
    const int* w = (const int*)d_in[2];
    const int* wexp = (const int*)d_in[3];
    float* out = (float*)d_out;

    k_transpose<<<(NB * HH * WW * 2) / 256, 256>>>(act, w);
    k_conv<0><<<NB * 32, 256>>>(expin, wexp, out, out_size);  // max pass
    k_conv<1><<<NB * 32, 256>>>(expin, wexp, out, out_size);  // quantize pass
}

// round 11
// speedup vs baseline: 1.4465x; 1.0055x over previous
#include <cuda_runtime.h>
#include <stdint.h>

#define NB 32
#define CI 32
#define CO 32
#define HH 128
#define WW 128

// Scratch (static __device__ arrays: allocation-free, graph-safe)
__device__ signed char g_act_nhwc[(size_t)NB * HH * WW * CI];  // 16 MB NHWC int8
__device__ int g_max;
__device__ unsigned g_wpack[CO * 9 * 8];                       // packed weights

// NCHW int32 -> NHWC int8. One thread = one 16B output chunk (pixel, ci-half).
// Reads: 64B-coalesced per ci; writes: fully contiguous STG.128.
// Block 0 also packs weights + resets g_max.
__global__ void k_transpose(const int* __restrict__ act, const int* __restrict__ w) {
    int idx = blockIdx.x * blockDim.x + threadIdx.x;  // NB*HH*WW*2 threads
    int half = idx & 1;
    int p = idx >> 1;              // pixel: n*16384 + y*128 + x
    int x = p & (WW - 1);
    int y = (p >> 7) & (HH - 1);
    int n = p >> 14;

    const int* src = act + ((size_t)(n * CI + half * 16) * HH + y) * WW + x;
    unsigned vv[4];
#pragma unroll
    for (int j = 0; j < 4; j++) {
        unsigned v = 0;
#pragma unroll
        for (int bb = 0; bb < 4; bb++) {
            unsigned c = (unsigned)src[(size_t)(j * 4 + bb) * HH * WW] & 0xFFu;
            v |= c << (8 * bb);
        }
        vv[j] = v;
    }
    *(uint4*)(g_act_nhwc + ((size_t)p << 5) + (half << 4)) =
        make_uint4(vv[0], vv[1], vv[2], vv[3]);

    if (blockIdx.x == 0) {
        if (threadIdx.x == 0) g_max = 0;
        for (int i = threadIdx.x; i < CO * 9 * 8; i += blockDim.x) {
            int ciw = i & 7;
            int t = (i >> 3) % 9;
            int co = i / 72;
            int kh = t / 3, kw = t - kh * 3;
            unsigned v = 0;
#pragma unroll
            for (int j = 0; j < 4; j++) {
                int ci = ciw * 4 + j;
                unsigned b = (unsigned)(w[((co * CI + ci) * 3 + kh) * 3 + kw]) & 0xFFu;
                v |= b << (8 * j);
            }
            g_wpack[i] = v;
        }
    }
}

__device__ __forceinline__ void mma_s8(int d[4], const unsigned a[4],
                                       unsigned b0, unsigned b1) {
    asm volatile(
        "mma.sync.aligned.m16n8k32.row.col.s32.s8.s8.s32 "
        "{%0,%1,%2,%3}, {%4,%5,%6,%7}, {%8,%9}, {%0,%1,%2,%3};\n"
        : "+r"(d[0]), "+r"(d[1]), "+r"(d[2]), "+r"(d[3])
        : "r"(a[0]), "r"(a[1]), "r"(a[2]), "r"(a[3]), "r"(b0), "r"(b1));
}

__device__ __forceinline__ void ldm4(unsigned r[4], unsigned saddr) {
    asm volatile(
        "ldmatrix.sync.aligned.m8n8.x4.shared.b16 {%0,%1,%2,%3}, [%4];\n"
        : "=r"(r[0]), "=r"(r[1]), "=r"(r[2]), "=r"(r[3])
        : "r"(saddr));
}

// swizzle: XOR bit4 with bit7 of the byte offset
__device__ __forceinline__ unsigned swz(unsigned off) {
    return off ^ ((off >> 3) & 16);
}

// Bit-exact replica of psto_shift + act_calc select paths.
__device__ __forceinline__ float quantize_one(int v, int shift, int eff) {
    if (shift < 1) return (float)(signed char)v;  // truncating int8 cast
    int rt = v >> eff;                            // floor division by 2^eff
    int prob = v & ((1 << eff) - 1);              // non-negative remainder
    int h = eff >> 1;
    int qp = prob >> h;
    int pr = prob & ((1 << h) - 1);
    if (eff & 1) pr <<= 1;
    int sgn = (v >> 31) | 1;                      // v==0 never decrements (prob=0)
    int r = rt + ((qp <= pr) ? 0 : sgn);
    r = r < -127 ? -127 : (r > 127 ? 127 : r);
    return (float)r;
}

// Implicit-GEMM conv via IMMA + ldmatrix. Block = 4 output rows (n fixed).
// 8 warps: warp w -> rows r0=(w>>2)*2 .. +1, x-segment (w&3)*32.
// Warp tile = 2 rows x 32 px x 32 co. Mainloop reorganized for A-row reuse:
// for kx: cache 3 B taps in regs, load each of 4 distinct A rows once,
// accumulate into all valid (rr, ky=row-rr) pairs. 42 ldm4/warp vs 54.
// MODE 0: |max| only. MODE 1: quantize + float store.
template <int MODE>
__global__ void __launch_bounds__(256) k_conv(const int* __restrict__ expin,
                                              const int* __restrict__ wexp,
                                              float* __restrict__ out,
                                              int out_size) {
    __shared__ __align__(128) signed char s_act[6 * 130 * 32];  // swizzled
    __shared__ __align__(128) signed char s_w[9 * 32 * 32];     // swizzled

    int tid = threadIdx.x;
    int b = blockIdx.x;
    int n = b >> 5;
    int y0 = (b & 31) << 2;

    // zero act tile (halo rows/cols)
    uint4* sa4 = (uint4*)s_act;
#pragma unroll
    for (int i = tid; i < 6 * 130 * 32 / 16; i += 256) sa4[i] = make_uint4(0, 0, 0, 0);
    // weights: (co,t,8 words) -> s_w[t][co] 32B rows, swizzled, 16B at a time
    for (int i = tid; i < 9 * 32 * 2; i += 256) {
        int h = i & 1;
        int co = (i >> 1) & 31;
        int t = i >> 6;
        unsigned off = ((unsigned)(t * 32 + co) << 5) + (h << 4);
        *(uint4*)(s_w + swz(off)) = ((const uint4*)g_wpack)[(co * 9 + t) * 2 + h];
    }
    __syncthreads();

    // fill interior: 6 rows x 128 px x 32B, swizzled
    {
        int px = tid >> 1;
        int half = (tid & 1) << 4;
#pragma unroll
        for (int r = 0; r < 6; r++) {
            int iy = y0 + r - 1;
            if ((unsigned)iy < HH) {
                const uint4* src = (const uint4*)(g_act_nhwc +
                    ((((size_t)n * HH + iy) * WW + px) << 5) + half);
                unsigned off = ((unsigned)((r * 130 + px + 1) << 5)) + half;
                *(uint4*)(s_act + swz(off)) = *src;
            }
        }
    }
    __syncthreads();

    int lane = tid & 31;
    int wid = tid >> 5;
    int r0 = (wid >> 2) << 1;
    int xbase = (wid & 3) << 5;

    unsigned actS = (unsigned)__cvta_generic_to_shared(s_act);
    unsigned wS = (unsigned)__cvta_generic_to_shared(s_w);

    // ldmatrix lane-dependent base offsets
    unsigned alane = ((unsigned)(lane & 15) << 5) + ((lane >> 4) << 4);
    unsigned bbase = ((unsigned)(((lane >> 4) << 3) + (lane & 7)) << 5) +
                     (((lane >> 3) & 1) << 4);

    int acc[2][2][4][4];  // [row][m][ns][k]
#pragma unroll
    for (int rr = 0; rr < 2; rr++)
#pragma unroll
        for (int m = 0; m < 2; m++)
#pragma unroll
            for (int ns = 0; ns < 4; ns++)
#pragma unroll
                for (int k = 0; k < 4; k++) acc[rr][m][ns][k] = 0;

#pragma unroll
    for (int kx = 0; kx < 3; kx++) {
        // cache B fragments for ky = 0,1,2 at this kx (taps t = ky*3+kx)
        unsigned bf[3][2][4];
#pragma unroll
        for (int ky = 0; ky < 3; ky++) {
            unsigned bo = bbase + ((unsigned)(ky * 3 + kx) << 10);
            ldm4(bf[ky][0], wS + swz(bo));
            ldm4(bf[ky][1], wS + swz(bo + 512));
        }
        // 4 distinct A rows; each feeds all valid (rr, ky = ra - rr)
#pragma unroll
        for (int ra = 0; ra < 4; ra++) {
            unsigned af[2][4];
            unsigned ao = alane +
                ((unsigned)((r0 + ra) * 130 + xbase + kx) << 5);
            ldm4(af[0], actS + swz(ao));
            ldm4(af[1], actS + swz(ao + 512));
#pragma unroll
            for (int rr = 0; rr < 2; rr++) {
                int ky = ra - rr;
                if (ky >= 0 && ky < 3) {
#pragma unroll
                    for (int m = 0; m < 2; m++) {
                        mma_s8(acc[rr][m][0], af[m], bf[ky][0][0], bf[ky][0][1]);
                        mma_s8(acc[rr][m][1], af[m], bf[ky][0][2], bf[ky][0][3]);
                        mma_s8(acc[rr][m][2], af[m], bf[ky][1][0], bf[ky][1][1]);
                        mma_s8(acc[rr][m][3], af[m], bf[ky][1][2], bf[ky][1][3]);
                    }
                }
            }
        }
    }

    int g = lane >> 2;
    int tig = lane & 3;

    if (MODE == 0) {
        int mloc = 0;
#pragma unroll
        for (int rr = 0; rr < 2; rr++)
#pragma unroll
            for (int m = 0; m < 2; m++)
#pragma unroll
                for (int ns = 0; ns < 4; ns++)
#pragma unroll
                    for (int k = 0; k < 4; k++) {
                        int a = acc[rr][m][ns][k];
                        mloc = max(mloc, a < 0 ? -a : a);
                    }
        mloc = __reduce_max_sync(0xffffffffu, mloc);
        if (lane == 0) atomicMax(&g_max, mloc);
    } else {
        int gmax = g_max;
        int bw = gmax ? (32 - __clz(gmax - 1)) : 0;  // exact ceil(log2)
        int shift = bw - 7;
        int eff = shift > 1 ? shift : 2;

#pragma unroll
        for (int rr = 0; rr < 2; rr++) {
            int y = y0 + r0 + rr;
#pragma unroll
            for (int m = 0; m < 2; m++)
#pragma unroll
                for (int ns = 0; ns < 4; ns++) {
                    int x0p = xbase + m * 16 + g;
                    int co0 = ns * 8 + tig * 2;
                    float* base0 = out + (((n * 32 + co0) * 128 + y) * 128);
                    float* base1 = base0 + 128 * 128;
                    base0[x0p] = quantize_one(acc[rr][m][ns][0], shift, eff);
                    base1[x0p] = quantize_one(acc[rr][m][ns][1], shift, eff);
                    base0[x0p + 8] = quantize_one(acc[rr][m][ns][2], shift, eff);
                    base1[x0p + 8] = quantize_one(acc[rr][m][ns][3], shift, eff);
                }
        }

        if (b == 0 && tid == 0) {
            int inc = shift > 1 ? shift : (shift == 1 ? 2 : 0);
            int e = expin[0] + wexp[0] + inc;
            out[out_size - 1] = (float)(signed char)e;
        }
    }
}

extern "C" void kernel_launch(void* const* d_in, const int* in_sizes, int n_in,
                              void* d_out, int out_size) {
    const int* act = (const int*)d_in[0];
    const int* expin = (const int*)d_in[1];
    const int* w = (const int*)d_in[2];
    const int* wexp = (const int*)d_in[3];
    float* out = (float*)d_out;

    k_transpose<<<(NB * HH * WW * 2) / 256, 256>>>(act, w);
    k_conv<0><<<NB * 32, 256>>>(expin, wexp, out, out_size);  // max pass
    k_conv<1><<<NB * 32, 256>>>(expin, wexp, out, out_size);  // quantize pass
}